// round 1
// baseline (speedup 1.0000x reference)
#include <cuda_runtime.h>
#include <math.h>

// Problem constants
#define LS       32
#define SB       1024            // S = LS*LS
#define NB       16              // batch
#define NE       1024            // embedding
#define BE       (NB*NE)         // 16384: stride between spatial positions
#define S_TOT    (SB*NB*NE)      // 16,777,216 elements

// Scratch for directions 1..3 (direction 0 goes straight into d_out)
__device__ float g_scr[3][S_TOT];

__device__ __forceinline__ float sigm(float v) { return 1.0f / (1.0f + expf(-v)); }

// ---------------------------------------------------------------------------
// Scan kernel: one thread per (dir, b, e). Runs the 2D SSM recurrence
// (= causal 2D conv with the impulse response) on the direction-flipped
// image, plus the two 1D boundary-correction recurrences (s along j, t
// along i) that implement the reference's K row0/col0 doubling.
//
//   x_v[i,j] = A3*x_h[i-1,j] + A4*x_v[i-1,j] + B2*u[i,j]
//   x_h[i,j] = A1*x_h[i,j-1] + A2*x_v[i,j-1] + B1*u[i,j]   (x_v of same row)
//   s[i,j]   = A1*s[i,j-1]  + w *u[i,j-1],  w  = A1B1+A2B2  (row-0 corr)
//   t[i,j]   = A4*t[i-1,j]  + w2*u[i-1,j],  w2 = A3B1+A4B2  (col-0 corr)
//   y[i,j]   = scale*( C1.(x_h+s) + C2.(x_v+t) )
//
// 8-row register blocking; cross-row state rows (x_h, x_v, t) live in
// thread-private SMEM slots [j][tid] (conflict-free, no syncs needed).
// ---------------------------------------------------------------------------
__global__ void __launch_bounds__(64) ssm_scan(
    const float* __restrict__ x,
    const float* __restrict__ A1v, const float* __restrict__ A2v,
    const float* __restrict__ A3v, const float* __restrict__ A4v,
    const float* __restrict__ B1v, const float* __restrict__ B2v,
    const float* __restrict__ C1v, const float* __restrict__ C2v,
    float* __restrict__ out)
{
    __shared__ float2 sh_xh[LS][64];
    __shared__ float2 sh_xv[LS][64];
    __shared__ float2 sh_t [LS][64];

    const int tid = threadIdx.x;
    const int g   = blockIdx.x * 64 + tid;
    const int e   = g & (NE - 1);
    const int b   = (g >> 10) & (NB - 1);
    const int dir = g >> 14;                 // 0..3
    const int h   = (dir << 6) | (e & 63);   // kernel channel
    const bool fi = (dir & 1) != 0;          // flip rows (axis -2)
    const bool fj = (dir & 2) != 0;          // flip cols (axis -1)

    const float scale = 0.70710678118654752440f;  // sqrt(1/N), N=2

    float a1[2], a2[2], a3[2], a4[2], bb1[2], bb2[2], c1[2], c2[2], w[2], w2[2];
#pragma unroll
    for (int n = 0; n < 2; n++) {
        a1[n]  = sigm(A1v[2 * h + n]);
        a2[n]  = sigm(A2v[2 * h + n]);
        a3[n]  = sigm(A3v[2 * h + n]);
        a4[n]  = sigm(A4v[2 * h + n]);
        bb1[n] = sigm(B1v[2 * h + n]);
        bb2[n] = sigm(B2v[2 * h + n]);
        c1[n]  = scale * C1v[2 * h + n];
        c2[n]  = scale * C2v[2 * h + n];
        w[n]   = a1[n] * bb1[n] + a2[n] * bb2[n];
        w2[n]  = a3[n] * bb1[n] + a4[n] * bb2[n];
    }

    // zero the private state rows (no cross-thread sharing -> no syncs)
#pragma unroll
    for (int j = 0; j < LS; j++) {
        sh_xh[j][tid] = make_float2(0.f, 0.f);
        sh_xv[j][tid] = make_float2(0.f, 0.f);
        sh_t [j][tid] = make_float2(0.f, 0.f);
    }

    const float* xp = x + b * NE + e;
    float* obuf = (dir == 0) ? out : g_scr[dir - 1];
    float* op   = obuf + b * NE + e;

    for (int ib = 0; ib < 4; ib++) {
        // per-row horizontal states for the 8 rows of this block
        float xh0[8], xh1[8], xv0[8], xv1[8], s0a[8], s1a[8], up[8];
#pragma unroll
        for (int r = 0; r < 8; r++) {
            xh0[r] = xh1[r] = xv0[r] = xv1[r] = s0a[r] = s1a[r] = up[r] = 0.f;
        }
        int rowoff[8];
#pragma unroll
        for (int r = 0; r < 8; r++) {
            int i  = ib * 8 + r;
            int ip = fi ? (LS - 1 - i) : i;
            rowoff[r] = (ip * LS) * BE;
        }

        for (int j = 0; j < LS; j++) {
            const int jp = fj ? (LS - 1 - j) : j;
            const int jB = jp * BE;

            float u[8];
#pragma unroll
            for (int r = 0; r < 8; r++) u[r] = xp[rowoff[r] + jB];

            float2 hup = sh_xh[j][tid];   // x_h of row above (block entry)
            float2 vup = sh_xv[j][tid];   // x_v of row above
            float2 tc  = sh_t [j][tid];   // t at first row of block

#pragma unroll
            for (int r = 0; r < 8; r++) {
                const float uu = u[r];
                // vertical state (needs row above at same column)
                float nv0 = a3[0] * hup.x + a4[0] * vup.x + bb2[0] * uu;
                float nv1 = a3[1] * hup.y + a4[1] * vup.y + bb2[1] * uu;
                // horizontal state (needs same row, previous column)
                float nh0 = a1[0] * xh0[r] + a2[0] * xv0[r] + bb1[0] * uu;
                float nh1 = a1[1] * xh1[r] + a2[1] * xv1[r] + bb1[1] * uu;
                // row-0 boundary correction (j recurrence, uses u[i,j-1])
                float ns0 = a1[0] * s0a[r] + w[0] * up[r];
                float ns1 = a1[1] * s1a[r] + w[1] * up[r];
                // output: scale*(C1.(xh+s) + C2.(xv+t))
                float y = c1[0] * (nh0 + ns0) + c1[1] * (nh1 + ns1)
                        + c2[0] * (nv0 + tc.x) + c2[1] * (nv1 + tc.y);
                op[rowoff[r] + jB] = y;
                // col-0 boundary correction (i recurrence, uses u[i-1,j])
                tc.x = a4[0] * tc.x + w2[0] * uu;
                tc.y = a4[1] * tc.y + w2[1] * uu;
                // roll states
                hup.x = nh0; hup.y = nh1;
                vup.x = nv0; vup.y = nv1;
                xh0[r] = nh0; xh1[r] = nh1;
                xv0[r] = nv0; xv1[r] = nv1;
                s0a[r] = ns0; s1a[r] = ns1;
                up[r]  = uu;
            }
            sh_xh[j][tid] = hup;
            sh_xv[j][tid] = vup;
            sh_t [j][tid] = tc;
        }
    }
}

// ---------------------------------------------------------------------------
// Epilogue: out = silu( y0+y1+y2+y3 + x*omega ), vectorized float4.
// ---------------------------------------------------------------------------
__global__ void __launch_bounds__(256) ssm_epilogue(
    const float* __restrict__ x,
    const float* __restrict__ omega,
    float* __restrict__ out)
{
    const int idx = (blockIdx.x * 256 + threadIdx.x) * 4;
    float4 v  = *reinterpret_cast<float4*>(out + idx);
    float4 s0 = *reinterpret_cast<const float4*>(&g_scr[0][idx]);
    float4 s1 = *reinterpret_cast<const float4*>(&g_scr[1][idx]);
    float4 s2 = *reinterpret_cast<const float4*>(&g_scr[2][idx]);
    float4 xv = *reinterpret_cast<const float4*>(x + idx);
    const int e = idx & (NE - 1);
    float4 om = *reinterpret_cast<const float4*>(omega + e);

    float z0 = v.x + s0.x + s1.x + s2.x + xv.x * om.x;
    float z1 = v.y + s0.y + s1.y + s2.y + xv.y * om.y;
    float z2 = v.z + s0.z + s1.z + s2.z + xv.z * om.z;
    float z3 = v.w + s0.w + s1.w + s2.w + xv.w * om.w;

    float4 r;
    r.x = z0 / (1.0f + expf(-z0));
    r.y = z1 / (1.0f + expf(-z1));
    r.z = z2 / (1.0f + expf(-z2));
    r.w = z3 / (1.0f + expf(-z3));
    *reinterpret_cast<float4*>(out + idx) = r;
}

extern "C" void kernel_launch(void* const* d_in, const int* in_sizes, int n_in,
                              void* d_out, int out_size)
{
    const float* x   = (const float*)d_in[0];
    const float* A1v = (const float*)d_in[1];
    const float* A2v = (const float*)d_in[2];
    const float* A3v = (const float*)d_in[3];
    const float* A4v = (const float*)d_in[4];
    const float* B1v = (const float*)d_in[5];
    const float* B2v = (const float*)d_in[6];
    const float* C1v = (const float*)d_in[7];
    const float* C2v = (const float*)d_in[8];
    const float* om  = (const float*)d_in[9];
    float* out = (float*)d_out;

    // 4 dirs * 16 b * 1024 e = 65536 threads
    ssm_scan<<<65536 / 64, 64>>>(x, A1v, A2v, A3v, A4v, B1v, B2v, C1v, C2v, out);
    ssm_epilogue<<<S_TOT / 4 / 256, 256>>>(x, om, out);
}

// round 2
// speedup vs baseline: 1.0210x; 1.0210x over previous
#include <cuda_runtime.h>
#include <math.h>

// Problem constants
#define LS       32
#define SB       1024            // S = LS*LS
#define NB       16              // batch
#define NE       1024            // embedding
#define BE       (NB*NE)         // 16384: stride between spatial positions
#define S_TOT    (SB*NB*NE)      // 16,777,216 elements

// Scratch for directions 1..3 (direction 0 goes straight into d_out)
__device__ float g_scr[3][S_TOT];

typedef unsigned long long u64;

__device__ __forceinline__ float sigm(float v) { return 1.0f / (1.0f + expf(-v)); }

// ---- packed f32x2 helpers (sm_103a paired-fp32 ops, PTX-only) ----
__device__ __forceinline__ u64 pack2(float lo, float hi) {
    u64 r; asm("mov.b64 %0, {%1,%2};" : "=l"(r) : "f"(lo), "f"(hi)); return r;
}
__device__ __forceinline__ float2 unpack2(u64 v) {
    float2 r; asm("mov.b64 {%0,%1}, %2;" : "=f"(r.x), "=f"(r.y) : "l"(v)); return r;
}
__device__ __forceinline__ u64 fma2(u64 a, u64 b, u64 c) {
    u64 d; asm("fma.rn.f32x2 %0,%1,%2,%3;" : "=l"(d) : "l"(a), "l"(b), "l"(c)); return d;
}
__device__ __forceinline__ u64 mul2(u64 a, u64 b) {
    u64 d; asm("mul.rn.f32x2 %0,%1,%2;" : "=l"(d) : "l"(a), "l"(b)); return d;
}
__device__ __forceinline__ u64 add2(u64 a, u64 b) {
    u64 d; asm("add.rn.f32x2 %0,%1,%2;" : "=l"(d) : "l"(a), "l"(b)); return d;
}

// ---------------------------------------------------------------------------
// Scan kernel: one thread per (dir, b, e). 2D SSM recurrence (= the causal 2D
// conv with the impulse response) on the direction-flipped image, plus the
// two 1D boundary-correction recurrences implementing the reference's
// K row-0 / col-0 doubling. N=2 state pairs packed into f32x2.
//
//   nv[i,j] = z[i-1,j] + B2*u            (z = A3*xh + A4*xv, folded carry)
//   nh[i,j] = A1*xh[i,j-1] + A2*xv[i,j-1] + B1*u
//   z [i,j] = A3*nh + A4*nv
//   ns[i,j] = A1*s + w*u[i,j-1],   w  = A1B1+A2B2   (row-0 corr)
//   t [i+1,j]= A4*t + w2*u[i,j],   w2 = A3B1+A4B2   (col-0 corr)
//   y = scale*( C1.(nh+ns) + C2.(nv+t) )
//
// Per-j cross-row state = {z, t} = 16B/thread -> 32KB/block -> 7 blocks/SM.
// ---------------------------------------------------------------------------
__global__ void __launch_bounds__(64) ssm_scan(
    const float* __restrict__ x,
    const float* __restrict__ A1v, const float* __restrict__ A2v,
    const float* __restrict__ A3v, const float* __restrict__ A4v,
    const float* __restrict__ B1v, const float* __restrict__ B2v,
    const float* __restrict__ C1v, const float* __restrict__ C2v,
    float* __restrict__ out)
{
    __shared__ u64 sh_z[LS][64];
    __shared__ u64 sh_t[LS][64];

    const int tid = threadIdx.x;
    const int g   = blockIdx.x * 64 + tid;
    const int e   = g & (NE - 1);
    const int b   = (g >> 10) & (NB - 1);
    const int dir = g >> 14;                 // 0..3
    const int h   = (dir << 6) | (e & 63);   // kernel channel
    const bool fi = (dir & 1) != 0;          // flip rows (axis -2)
    const bool fj = (dir & 2) != 0;          // flip cols (axis -1)

    const float scale = 0.70710678118654752440f;  // sqrt(1/N), N=2

    float p1[2], p2[2], p3[2], p4[2], q1[2], q2[2], r1[2], r2[2], wv[2], w2v[2];
#pragma unroll
    for (int n = 0; n < 2; n++) {
        p1[n] = sigm(A1v[2 * h + n]);
        p2[n] = sigm(A2v[2 * h + n]);
        p3[n] = sigm(A3v[2 * h + n]);
        p4[n] = sigm(A4v[2 * h + n]);
        q1[n] = sigm(B1v[2 * h + n]);
        q2[n] = sigm(B2v[2 * h + n]);
        r1[n] = scale * C1v[2 * h + n];
        r2[n] = scale * C2v[2 * h + n];
        wv[n]  = p1[n] * q1[n] + p2[n] * q2[n];
        w2v[n] = p3[n] * q1[n] + p4[n] * q2[n];
    }
    const u64 a1 = pack2(p1[0], p1[1]);
    const u64 a2 = pack2(p2[0], p2[1]);
    const u64 a3 = pack2(p3[0], p3[1]);
    const u64 a4 = pack2(p4[0], p4[1]);
    const u64 bb1 = pack2(q1[0], q1[1]);
    const u64 bb2 = pack2(q2[0], q2[1]);
    const u64 c1 = pack2(r1[0], r1[1]);
    const u64 c2 = pack2(r2[0], r2[1]);
    const u64 w  = pack2(wv[0], wv[1]);
    const u64 w2 = pack2(w2v[0], w2v[1]);

    // zero the private per-column states (no cross-thread sharing -> no syncs)
#pragma unroll
    for (int j = 0; j < LS; j++) {
        sh_z[j][tid] = 0ULL;
        sh_t[j][tid] = 0ULL;
    }

    const float* xp = x + b * NE + e;
    float* obuf = (dir == 0) ? out : g_scr[dir - 1];
    float* op   = obuf + b * NE + e;

    for (int ib = 0; ib < 4; ib++) {
        // per-row horizontal states for the 8 rows of this block
        u64 xh[8], xv[8], ss[8], wu[8];
#pragma unroll
        for (int r = 0; r < 8; r++) { xh[r] = xv[r] = ss[r] = wu[r] = 0ULL; }

        int rowoff[8];
#pragma unroll
        for (int r = 0; r < 8; r++) {
            int i  = ib * 8 + r;
            int ip = fi ? (LS - 1 - i) : i;
            rowoff[r] = (ip * LS) * BE;
        }

        for (int j = 0; j < LS; j++) {
            const int jp = fj ? (LS - 1 - j) : j;
            const int jB = jp * BE;

            float u[8];
#pragma unroll
            for (int r = 0; r < 8; r++) u[r] = xp[rowoff[r] + jB];

            u64 z = sh_z[j][tid];   // folded vertical carry from row above
            u64 t = sh_t[j][tid];   // col-0 correction state

#pragma unroll
            for (int r = 0; r < 8; r++) {
                const u64 u2 = pack2(u[r], u[r]);
                // vertical state
                u64 nv = fma2(bb2, u2, z);
                // horizontal state
                u64 nh = fma2(a1, xh[r], fma2(a2, xv[r], mul2(bb1, u2)));
                // folded carry for next row
                z = fma2(a4, nv, mul2(a3, nh));
                // row-0 boundary correction (uses u[i,j-1])
                u64 ns = fma2(a1, ss[r], wu[r]);
                // output: scale*(C1.(nh+ns) + C2.(nv+t))
                u64 acc = fma2(c2, add2(nv, t), mul2(c1, add2(nh, ns)));
                float2 av = unpack2(acc);
                op[rowoff[r] + jB] = av.x + av.y;
                // col-0 boundary correction (uses u[i-1,j])
                t = fma2(a4, t, mul2(w2, u2));
                // roll states
                xh[r] = nh; xv[r] = nv; ss[r] = ns;
                wu[r] = mul2(w, u2);
            }
            sh_z[j][tid] = z;
            sh_t[j][tid] = t;
        }
    }
}

// ---------------------------------------------------------------------------
// Epilogue: out = silu( y0+y1+y2+y3 + x*omega ), vectorized float4.
// ---------------------------------------------------------------------------
__global__ void __launch_bounds__(256) ssm_epilogue(
    const float* __restrict__ x,
    const float* __restrict__ omega,
    float* __restrict__ out)
{
    const int idx = (blockIdx.x * 256 + threadIdx.x) * 4;
    float4 v  = *reinterpret_cast<float4*>(out + idx);
    float4 s0 = *reinterpret_cast<const float4*>(&g_scr[0][idx]);
    float4 s1 = *reinterpret_cast<const float4*>(&g_scr[1][idx]);
    float4 s2 = *reinterpret_cast<const float4*>(&g_scr[2][idx]);
    float4 xv = *reinterpret_cast<const float4*>(x + idx);
    const int e = idx & (NE - 1);
    float4 om = *reinterpret_cast<const float4*>(omega + e);

    float z0 = v.x + s0.x + s1.x + s2.x + xv.x * om.x;
    float z1 = v.y + s0.y + s1.y + s2.y + xv.y * om.y;
    float z2 = v.z + s0.z + s1.z + s2.z + xv.z * om.z;
    float z3 = v.w + s0.w + s1.w + s2.w + xv.w * om.w;

    float4 r;
    r.x = z0 / (1.0f + expf(-z0));
    r.y = z1 / (1.0f + expf(-z1));
    r.z = z2 / (1.0f + expf(-z2));
    r.w = z3 / (1.0f + expf(-z3));
    *reinterpret_cast<float4*>(out + idx) = r;
}

extern "C" void kernel_launch(void* const* d_in, const int* in_sizes, int n_in,
                              void* d_out, int out_size)
{
    const float* x   = (const float*)d_in[0];
    const float* A1v = (const float*)d_in[1];
    const float* A2v = (const float*)d_in[2];
    const float* A3v = (const float*)d_in[3];
    const float* A4v = (const float*)d_in[4];
    const float* B1v = (const float*)d_in[5];
    const float* B2v = (const float*)d_in[6];
    const float* C1v = (const float*)d_in[7];
    const float* C2v = (const float*)d_in[8];
    const float* om  = (const float*)d_in[9];
    float* out = (float*)d_out;

    // 4 dirs * 16 b * 1024 e = 65536 threads; 1024 blocks <= 148*7 -> 1 wave
    ssm_scan<<<65536 / 64, 64>>>(x, A1v, A2v, A3v, A4v, B1v, B2v, C1v, C2v, out);
    ssm_epilogue<<<S_TOT / 4 / 256, 256>>>(x, om, out);
}

// round 3
// speedup vs baseline: 1.5414x; 1.5097x over previous
#include <cuda_runtime.h>
#include <cuda_fp16.h>
#include <math.h>

// Problem constants
#define LS       32
#define SB       1024            // S = LS*LS
#define NB       16              // batch
#define NE       1024            // embedding
#define BE       (NB*NE)         // 16384: stride between spatial positions
#define S_TOT    (SB*NB*NE)      // 16,777,216 elements

// fp16 scratch for all 4 direction outputs (128 MB)
__device__ __half g_scrh[4][S_TOT];

typedef unsigned long long u64;

__device__ __forceinline__ float sigm(float v) { return 1.0f / (1.0f + expf(-v)); }

// ---- packed f32x2 helpers (sm_103a paired-fp32 ops, PTX-only) ----
__device__ __forceinline__ u64 pack2(float lo, float hi) {
    u64 r; asm("mov.b64 %0, {%1,%2};" : "=l"(r) : "f"(lo), "f"(hi)); return r;
}
__device__ __forceinline__ float2 unpack2(u64 v) {
    float2 r; asm("mov.b64 {%0,%1}, %2;" : "=f"(r.x), "=f"(r.y) : "l"(v)); return r;
}
__device__ __forceinline__ u64 fma2(u64 a, u64 b, u64 c) {
    u64 d; asm("fma.rn.f32x2 %0,%1,%2,%3;" : "=l"(d) : "l"(a), "l"(b), "l"(c)); return d;
}
__device__ __forceinline__ u64 mul2(u64 a, u64 b) {
    u64 d; asm("mul.rn.f32x2 %0,%1,%2;" : "=l"(d) : "l"(a), "l"(b)); return d;
}
__device__ __forceinline__ u64 add2(u64 a, u64 b) {
    u64 d; asm("add.rn.f32x2 %0,%1,%2;" : "=l"(d) : "l"(a), "l"(b)); return d;
}

__device__ __forceinline__ void st_half_cs(__half* p, float v) {
    unsigned short h = __half_as_ushort(__float2half_rn(v));
    asm volatile("st.global.cs.u16 [%0], %1;" :: "l"(p), "h"(h) : "memory");
}

// ---------------------------------------------------------------------------
// Scan kernel: one thread per (dir, b, e). 2D SSM recurrence (= the causal 2D
// conv with the impulse response) on the direction-flipped image, plus the
// two 1D boundary-correction recurrences implementing the reference's
// K row-0 / col-0 doubling. N=2 state pairs packed into f32x2.
// Input loads for column j+1 are prefetched (double-buffered) while
// computing column j, hiding L2/DRAM latency behind ~200cyc of fma work.
// ---------------------------------------------------------------------------
__global__ void __launch_bounds__(64, 7) ssm_scan(
    const float* __restrict__ x,
    const float* __restrict__ A1v, const float* __restrict__ A2v,
    const float* __restrict__ A3v, const float* __restrict__ A4v,
    const float* __restrict__ B1v, const float* __restrict__ B2v,
    const float* __restrict__ C1v, const float* __restrict__ C2v)
{
    __shared__ u64 sh_z[LS][64];
    __shared__ u64 sh_t[LS][64];

    const int tid = threadIdx.x;
    const int g   = blockIdx.x * 64 + tid;
    const int e   = g & (NE - 1);
    const int b   = (g >> 10) & (NB - 1);
    const int dir = g >> 14;                 // 0..3
    const int h   = (dir << 6) | (e & 63);   // kernel channel
    const bool fi = (dir & 1) != 0;          // flip rows (axis -2)
    const bool fj = (dir & 2) != 0;          // flip cols (axis -1)

    const float scale = 0.70710678118654752440f;  // sqrt(1/N), N=2

    float p1[2], p2[2], p3[2], p4[2], q1[2], q2[2], r1[2], r2[2], wv[2], w2v[2];
#pragma unroll
    for (int n = 0; n < 2; n++) {
        p1[n] = sigm(A1v[2 * h + n]);
        p2[n] = sigm(A2v[2 * h + n]);
        p3[n] = sigm(A3v[2 * h + n]);
        p4[n] = sigm(A4v[2 * h + n]);
        q1[n] = sigm(B1v[2 * h + n]);
        q2[n] = sigm(B2v[2 * h + n]);
        r1[n] = scale * C1v[2 * h + n];
        r2[n] = scale * C2v[2 * h + n];
        wv[n]  = p1[n] * q1[n] + p2[n] * q2[n];
        w2v[n] = p3[n] * q1[n] + p4[n] * q2[n];
    }
    const u64 a1 = pack2(p1[0], p1[1]);
    const u64 a2 = pack2(p2[0], p2[1]);
    const u64 a3 = pack2(p3[0], p3[1]);
    const u64 a4 = pack2(p4[0], p4[1]);
    const u64 bb1 = pack2(q1[0], q1[1]);
    const u64 bb2 = pack2(q2[0], q2[1]);
    const u64 c1 = pack2(r1[0], r1[1]);
    const u64 c2 = pack2(r2[0], r2[1]);
    const u64 w  = pack2(wv[0], wv[1]);
    const u64 w2 = pack2(w2v[0], w2v[1]);

    // zero the private per-column states (no cross-thread sharing -> no syncs)
#pragma unroll
    for (int j = 0; j < LS; j++) {
        sh_z[j][tid] = 0ULL;
        sh_t[j][tid] = 0ULL;
    }

    const float* xp = x + b * NE + e;
    __half* op = g_scrh[dir] + b * NE + e;

    for (int ib = 0; ib < 4; ib++) {
        // per-row horizontal states for the 8 rows of this block
        u64 xh[8], xv[8], ss[8], wu[8];
#pragma unroll
        for (int r = 0; r < 8; r++) { xh[r] = xv[r] = ss[r] = wu[r] = 0ULL; }

        int rowoff[8];
#pragma unroll
        for (int r = 0; r < 8; r++) {
            int i  = ib * 8 + r;
            int ip = fi ? (LS - 1 - i) : i;
            rowoff[r] = (ip * LS) * BE;
        }

        // prefetch column j=0
        float u_cur[8], u_nxt[8];
        {
            const int jp0 = fj ? (LS - 1) : 0;
            const int jB0 = jp0 * BE;
#pragma unroll
            for (int r = 0; r < 8; r++) u_cur[r] = xp[rowoff[r] + jB0];
        }

        for (int j = 0; j < LS; j++) {
            const int jp = fj ? (LS - 1 - j) : j;
            const int jB = jp * BE;

            // issue next column's loads before consuming this column
            if (j < LS - 1) {
                const int jpn = fj ? (LS - 2 - j) : (j + 1);
                const int jBn = jpn * BE;
#pragma unroll
                for (int r = 0; r < 8; r++) u_nxt[r] = xp[rowoff[r] + jBn];
            }

            u64 z = sh_z[j][tid];   // folded vertical carry from row above
            u64 t = sh_t[j][tid];   // col-0 correction state

#pragma unroll
            for (int r = 0; r < 8; r++) {
                const u64 u2 = pack2(u_cur[r], u_cur[r]);
                // vertical state
                u64 nv = fma2(bb2, u2, z);
                // horizontal state
                u64 nh = fma2(a1, xh[r], fma2(a2, xv[r], mul2(bb1, u2)));
                // folded carry for next row
                z = fma2(a4, nv, mul2(a3, nh));
                // row-0 boundary correction (uses u[i,j-1])
                u64 ns = fma2(a1, ss[r], wu[r]);
                // output: scale*(C1.(nh+ns) + C2.(nv+t))
                u64 acc = fma2(c2, add2(nv, t), mul2(c1, add2(nh, ns)));
                float2 av = unpack2(acc);
                st_half_cs(op + rowoff[r] + jB, av.x + av.y);
                // col-0 boundary correction (uses u[i-1,j])
                t = fma2(a4, t, mul2(w2, u2));
                // roll states
                xh[r] = nh; xv[r] = nv; ss[r] = ns;
                wu[r] = mul2(w, u2);
            }
            sh_z[j][tid] = z;
            sh_t[j][tid] = t;

#pragma unroll
            for (int r = 0; r < 8; r++) u_cur[r] = u_nxt[r];
        }
    }
}

// ---------------------------------------------------------------------------
// Epilogue: out = silu( y0+y1+y2+y3 + x*omega ). 8 elems/thread.
// Scratch reads are streaming (read-once) fp16.
// ---------------------------------------------------------------------------
__global__ void __launch_bounds__(256) ssm_epilogue(
    const float* __restrict__ x,
    const float* __restrict__ omega,
    float* __restrict__ out)
{
    const int idx = (blockIdx.x * 256 + threadIdx.x) * 8;

    // 4 direction partials, fp16, 8 values each = uint4
    float acc[8];
#pragma unroll
    for (int k = 0; k < 8; k++) acc[k] = 0.f;

#pragma unroll
    for (int d = 0; d < 4; d++) {
        uint4 raw = __ldcs(reinterpret_cast<const uint4*>(&g_scrh[d][idx]));
        const unsigned* rw = reinterpret_cast<const unsigned*>(&raw);
#pragma unroll
        for (int p = 0; p < 4; p++) {
            __half2 hv = *reinterpret_cast<const __half2*>(&rw[p]);
            float2 fv = __half22float2(hv);
            acc[2 * p + 0] += fv.x;
            acc[2 * p + 1] += fv.y;
        }
    }

    float4 x0 = *reinterpret_cast<const float4*>(x + idx);
    float4 x1 = *reinterpret_cast<const float4*>(x + idx + 4);
    const int e = idx & (NE - 1);
    float4 o0 = *reinterpret_cast<const float4*>(omega + e);
    float4 o1 = *reinterpret_cast<const float4*>(omega + e + 4);

    float z[8];
    z[0] = acc[0] + x0.x * o0.x;
    z[1] = acc[1] + x0.y * o0.y;
    z[2] = acc[2] + x0.z * o0.z;
    z[3] = acc[3] + x0.w * o0.w;
    z[4] = acc[4] + x1.x * o1.x;
    z[5] = acc[5] + x1.y * o1.y;
    z[6] = acc[6] + x1.z * o1.z;
    z[7] = acc[7] + x1.w * o1.w;

    float4 r0, r1;
    r0.x = z[0] / (1.0f + expf(-z[0]));
    r0.y = z[1] / (1.0f + expf(-z[1]));
    r0.z = z[2] / (1.0f + expf(-z[2]));
    r0.w = z[3] / (1.0f + expf(-z[3]));
    r1.x = z[4] / (1.0f + expf(-z[4]));
    r1.y = z[5] / (1.0f + expf(-z[5]));
    r1.z = z[6] / (1.0f + expf(-z[6]));
    r1.w = z[7] / (1.0f + expf(-z[7]));
    *reinterpret_cast<float4*>(out + idx)     = r0;
    *reinterpret_cast<float4*>(out + idx + 4) = r1;
}

extern "C" void kernel_launch(void* const* d_in, const int* in_sizes, int n_in,
                              void* d_out, int out_size)
{
    const float* x   = (const float*)d_in[0];
    const float* A1v = (const float*)d_in[1];
    const float* A2v = (const float*)d_in[2];
    const float* A3v = (const float*)d_in[3];
    const float* A4v = (const float*)d_in[4];
    const float* B1v = (const float*)d_in[5];
    const float* B2v = (const float*)d_in[6];
    const float* C1v = (const float*)d_in[7];
    const float* C2v = (const float*)d_in[8];
    const float* om  = (const float*)d_in[9];
    float* out = (float*)d_out;

    // 4 dirs * 16 b * 1024 e = 65536 threads; 1024 blocks <= 148*7 -> 1 wave
    ssm_scan<<<65536 / 64, 64>>>(x, A1v, A2v, A3v, A4v, B1v, B2v, C1v, C2v);
    ssm_epilogue<<<S_TOT / 8 / 256, 256>>>(x, om, out);
}